// round 9
// baseline (speedup 1.0000x reference)
#include <cuda_runtime.h>

// DilatedReparamBlock == single 13x13 depthwise conv + per-channel bias.
//
// R8 = R7 with the store bug fixed (R7 wrote only 8 of 16 output cols per
// thread -> rel_err 0.709). Compute path unchanged:
//   - packed fma.rn.f32x2 (2 FLOP-lanes per FMA issue slot)
//   - R6-proven conflict-free smem: 16B row swizzle shift(r)=4*((r>>1)&7),
//     SSTR=96, lane map (colb=lane>>3, pair=warp*8+lane&7)
//   - second tile shifted by one column -> every FFMA2 x-operand is a
//     direct aligned LDS128 (no ALU repacking)
//   - even-kx pass then odd-kx pass (one window live at a time)
//   - weights broadcast as one LDS128 (w_iy,w_iy,w_iy-1,w_iy-1) per kx.

#define CC 256
#define HW 56
#define PAD 6
#define SROWS 68
#define SSTR  96                 // floats/row (mult of 16; swizzle span 28)
#define NTHR 128

#define SX_ELEMS  (SROWS * SSTR)                  // 6528 floats
#define SMEM_BYTES (2 * SX_ELEMS * 4 + 14 * 13 * 16 + 16)

typedef unsigned long long u64;

__device__ float  g_weq[CC * 169];
__device__ float4 g_wq4[CC * 14 * 13];   // (w[iy],w[iy],w[iy-1],w[iy-1])
__device__ float  g_bias[CC];

static __device__ __forceinline__ void ffma2(u64& acc, u64 x2, u64 w2)
{
    asm("fma.rn.f32x2 %0, %1, %2, %0;" : "+l"(acc) : "l"(x2), "l"(w2));
}

__global__ void prep_kernel(const float* __restrict__ lk_w,
                            const float* __restrict__ w0, const float* __restrict__ w1,
                            const float* __restrict__ w2, const float* __restrict__ w3,
                            const float* __restrict__ w4, const float* __restrict__ w5,
                            const float* __restrict__ gamma, const float* __restrict__ beta,
                            const float* __restrict__ mean,  const float* __restrict__ var)
{
    __shared__ float sweq[169];
    int c = blockIdx.x;
    int t = threadIdx.x;

    float s[7], sh[7];
#pragma unroll
    for (int i = 0; i < 7; i++) {
        float sc = gamma[i * CC + c] * rsqrtf(var[i * CC + c] + 1e-5f);
        s[i]  = sc;
        sh[i] = beta[i * CC + c] - mean[i * CC + c] * sc;
    }
    if (t == 0)
        g_bias[c] = sh[0] + sh[1] + sh[2] + sh[3] + sh[4] + sh[5] + sh[6];

    if (t < 169) {
        int ty = t / 13, tx = t % 13;
        int dy = ty - PAD, dx = tx - PAD;
        float acc = s[0] * lk_w[c * 169 + t];

        const float* ws[6]   = { w0, w1, w2, w3, w4, w5 };
        const int    KSa[6]  = { 5, 7, 7, 3, 3, 3 };
        const int    DILa[6] = { 1, 1, 2, 3, 4, 5 };
#pragma unroll
        for (int j = 0; j < 6; j++) {
            int r = DILa[j], k = KSa[j];
            if (dy % r == 0 && dx % r == 0) {
                int a  = dy / r + (k - 1) / 2;
                int b2 = dx / r + (k - 1) / 2;
                if (a >= 0 && a < k && b2 >= 0 && b2 < k)
                    acc += s[j + 1] * ws[j][c * k * k + a * k + b2];
            }
        }
        sweq[t] = acc;
        g_weq[c * 169 + t] = acc;
    }
    __syncthreads();

    if (t < 14 * 13) {
        int iy = t / 13, kx = t % 13;
        float hi = (iy < 13) ? sweq[iy * 13 + kx]       : 0.f;
        float lo = (iy >= 1) ? sweq[(iy - 1) * 13 + kx] : 0.f;
        g_wq4[c * 182 + t] = make_float4(hi, hi, lo, lo);
    }
}

// One input row r = oy0+iy: accumulate into out rows oy0 (DO0, w row iy)
// and oy0+1 (DO1, w row iy-1).
template<bool DO0, bool DO1>
static __device__ __forceinline__ void row_pass(const float* __restrict__ sx,
                                                const float* __restrict__ sx2,
                                                const float4* __restrict__ swq,
                                                int r, int iy, int ox0,
                                                u64 acc0[8], u64 acc1[8])
{
    int off = r * SSTR + ((((unsigned)r >> 1) & 7) << 2) + ox0;
    const float4* wq = &swq[iy * 13];

    {   // even kx: operands from sx (pairs at even logical cols)
        const ulonglong2* xr = reinterpret_cast<const ulonglong2*>(&sx[off]);
        u64 xe[14];
#pragma unroll
        for (int q = 0; q < 7; q++) {
            ulonglong2 v = xr[q];
            xe[2 * q] = v.x; xe[2 * q + 1] = v.y;
        }
#pragma unroll
        for (int kh = 0; kh < 7; kh++) {            // kx = 2*kh
            float4 wf = wq[2 * kh];
            u64 whi, wlo;
            asm("mov.b64 %0, {%2, %3}; mov.b64 %1, {%4, %5};"
                : "=l"(whi), "=l"(wlo)
                : "f"(wf.x), "f"(wf.y), "f"(wf.z), "f"(wf.w));
#pragma unroll
            for (int o = 0; o < 8; o++) {
                u64 x2 = xe[kh + o];
                if (DO0) ffma2(acc0[o], x2, whi);
                if (DO1) ffma2(acc1[o], x2, wlo);
            }
        }
    }
    {   // odd kx: operands from shifted tile sx2
        const ulonglong2* xr = reinterpret_cast<const ulonglong2*>(&sx2[off]);
        u64 xo[14];
#pragma unroll
        for (int q = 0; q < 7; q++) {
            ulonglong2 v = xr[q];
            xo[2 * q] = v.x; xo[2 * q + 1] = v.y;
        }
#pragma unroll
        for (int kh = 0; kh < 6; kh++) {            // kx = 2*kh+1
            float4 wf = wq[2 * kh + 1];
            u64 whi, wlo;
            asm("mov.b64 %0, {%2, %3}; mov.b64 %1, {%4, %5};"
                : "=l"(whi), "=l"(wlo)
                : "f"(wf.x), "f"(wf.y), "f"(wf.z), "f"(wf.w));
#pragma unroll
            for (int o = 0; o < 8; o++) {
                u64 x2 = xo[kh + o];
                if (DO0) ffma2(acc0[o], x2, whi);
                if (DO1) ffma2(acc1[o], x2, wlo);
            }
        }
    }
}

__global__ void __launch_bounds__(NTHR, 4) conv_kernel(const float* __restrict__ x,
                                                       float* __restrict__ out)
{
    extern __shared__ float smem[];
    float*  sx   = smem;                          // swizzled X(r,c)
    float*  sx2  = smem + SX_ELEMS;               // swizzled X(r,c+1)
    float4* swq  = reinterpret_cast<float4*>(smem + 2 * SX_ELEMS);
    float*  sbp  = reinterpret_cast<float*>(swq + 182);

    int bc = blockIdx.x;
    const float* xim = x   + (size_t)bc * (HW * HW);
    float*       oim = out + (size_t)bc * (HW * HW);
    int tid = threadIdx.x;
    int c   = bc & (CC - 1);

    for (int idx = tid; idx < SX_ELEMS; idx += NTHR) {
        int r = idx / SSTR;
        int p = idx - r * SSTR;
        int shift = (((unsigned)r >> 1) & 7) << 2;
        int cl = p - shift;
        int iy = r - PAD, ix = cl - PAD;
        float v = 0.f, v2 = 0.f;
        if ((unsigned)iy < (unsigned)HW) {
            if ((unsigned)ix < (unsigned)HW)       v  = xim[iy * HW + ix];
            if ((unsigned)(ix + 1) < (unsigned)HW) v2 = xim[iy * HW + ix + 1];
        }
        sx[idx]  = v;
        sx2[idx] = v2;
    }
    for (int t = tid; t < 182; t += NTHR) swq[t] = g_wq4[c * 182 + t];
    if (tid == 0) *sbp = g_bias[c];
    __syncthreads();

    int warp = tid >> 5, lane = tid & 31;
    int colb = lane >> 3;                 // ox0 = colb*16
    int pair = warp * 8 + (lane & 7);     // active < 28
    if (pair >= 28) return;
    int oy0 = pair * 2;
    int ox0 = colb * 16;

    u64 acc0[8], acc1[8];
#pragma unroll
    for (int o = 0; o < 8; o++) { acc0[o] = 0ull; acc1[o] = 0ull; }

    row_pass<true, false>(sx, sx2, swq, oy0 + 0, 0, ox0, acc0, acc1);
#pragma unroll 1
    for (int iy = 1; iy <= 12; iy++)
        row_pass<true, true>(sx, sx2, swq, oy0 + iy, iy, ox0, acc0, acc1);
    row_pass<false, true>(sx, sx2, swq, oy0 + 13, 13, ox0, acc0, acc1);

    // Store all 16 columns: quad q covers cols ox0+4q..ox0+4q+3
    // from acc[2q], acc[2q+1]. colb 3 stores only cols 48..55 (q<2).
    float bb = *sbp;
    int nq = (colb == 3) ? 2 : 4;
    float4* o0 = reinterpret_cast<float4*>(&oim[oy0 * HW + ox0]);
    float4* o1 = reinterpret_cast<float4*>(&oim[(oy0 + 1) * HW + ox0]);
#pragma unroll
    for (int q = 0; q < 4; q++) {
        if (q < nq) {
            float4 r0, r1;
            r0.x = __uint_as_float((unsigned)(acc0[2*q]      )) + bb;
            r0.y = __uint_as_float((unsigned)(acc0[2*q] >> 32)) + bb;
            r0.z = __uint_as_float((unsigned)(acc0[2*q+1]      )) + bb;
            r0.w = __uint_as_float((unsigned)(acc0[2*q+1] >> 32)) + bb;
            r1.x = __uint_as_float((unsigned)(acc1[2*q]      )) + bb;
            r1.y = __uint_as_float((unsigned)(acc1[2*q] >> 32)) + bb;
            r1.z = __uint_as_float((unsigned)(acc1[2*q+1]      )) + bb;
            r1.w = __uint_as_float((unsigned)(acc1[2*q+1] >> 32)) + bb;
            o0[q] = r0;
            o1[q] = r1;
        }
    }
}

extern "C" void kernel_launch(void* const* d_in, const int* in_sizes, int n_in,
                              void* d_out, int out_size)
{
    const float* x    = (const float*)d_in[0];
    const float* lk_w = (const float*)d_in[1];
    const float* w0   = (const float*)d_in[2];
    const float* w1   = (const float*)d_in[3];
    const float* w2   = (const float*)d_in[4];
    const float* w3   = (const float*)d_in[5];
    const float* w4   = (const float*)d_in[6];
    const float* w5   = (const float*)d_in[7];
    const float* g    = (const float*)d_in[8];
    const float* b    = (const float*)d_in[9];
    const float* m    = (const float*)d_in[10];
    const float* v    = (const float*)d_in[11];
    float* out = (float*)d_out;

    // Idempotent, non-stream, capture-safe; called unconditionally (no
    // static guards per harness rules).
    cudaFuncSetAttribute(conv_kernel,
                         cudaFuncAttributeMaxDynamicSharedMemorySize,
                         SMEM_BYTES);

    prep_kernel<<<CC, 192>>>(lk_w, w0, w1, w2, w3, w4, w5, g, b, m, v);

    int nimg = out_size / (HW * HW);    // 8192
    conv_kernel<<<nimg, NTHR, SMEM_BYTES>>>(x, out);
}

// round 10
// speedup vs baseline: 2.0795x; 2.0795x over previous
#include <cuda_runtime.h>
#include <cstdint>

// DilatedReparamBlock == single 13x13 depthwise conv + per-channel bias.
//
// R9: fp32 ALU wall (~260us, confirmed by 3 structures) -> tensor cores.
// Block-Toeplitz implicit GEMM with tf32 mma.sync.m16n8k8:
//   O[y, xb*8+n] = sum_{ky<13, c20<20} Xp[y+ky][xb*8+c20] * B[(ky,c20)][n]
//   B[k][n] = Weq[ky][c20-n] if 0<=c20-n<=12 else 0   (K = 13*20 -> pad 264)
// CTA = (channel, 2 images): M = 2*56 = 112 = 7 m16-tiles, N = 8 (one xb
// per warp, 7 warps), K = 264 = 33 k8-steps. A-fragments read straight from
// the padded smem tiles (stride 68 == 4 mod 32 banks -> conflict-free).

#define CC   256
#define HW   56
#define PAD  6
#define TROWS 69              // 68 padded rows + 1 zero row for k-padding
#define TCOLS 68
#define TILE (TROWS * TCOLS)  // 4692
#define KTOT 264              // 33 * 8 (13*20 = 260 real + 4 zero)
#define NTHR 224              // 7 warps, warp w <-> xb = w

__device__ float    g_weq[CC * 169];
__device__ uint32_t g_B[CC * KTOT * 8];   // tf32 bits, layout [k][n]
__device__ float    g_bias[CC];

static __device__ __forceinline__ uint32_t f2tf32(float v)
{
    uint32_t u;
    asm("cvt.rna.tf32.f32 %0, %1;" : "=r"(u) : "f"(v));
    return u;
}

__global__ void prep_kernel(const float* __restrict__ lk_w,
                            const float* __restrict__ w0, const float* __restrict__ w1,
                            const float* __restrict__ w2, const float* __restrict__ w3,
                            const float* __restrict__ w4, const float* __restrict__ w5,
                            const float* __restrict__ gamma, const float* __restrict__ beta,
                            const float* __restrict__ mean,  const float* __restrict__ var)
{
    int c = blockIdx.x;
    int t = threadIdx.x;

    float s[7], sh[7];
#pragma unroll
    for (int i = 0; i < 7; i++) {
        float sc = gamma[i * CC + c] * rsqrtf(var[i * CC + c] + 1e-5f);
        s[i]  = sc;
        sh[i] = beta[i * CC + c] - mean[i * CC + c] * sc;
    }
    if (t == 0)
        g_bias[c] = sh[0] + sh[1] + sh[2] + sh[3] + sh[4] + sh[5] + sh[6];

    if (t < 169) {
        int ty = t / 13, tx = t % 13;
        int dy = ty - PAD, dx = tx - PAD;
        float acc = s[0] * lk_w[c * 169 + t];

        const float* ws[6]   = { w0, w1, w2, w3, w4, w5 };
        const int    KSa[6]  = { 5, 7, 7, 3, 3, 3 };
        const int    DILa[6] = { 1, 1, 2, 3, 4, 5 };
#pragma unroll
        for (int j = 0; j < 6; j++) {
            int r = DILa[j], k = KSa[j];
            if (dy % r == 0 && dx % r == 0) {
                int a  = dy / r + (k - 1) / 2;
                int b2 = dx / r + (k - 1) / 2;
                if (a >= 0 && a < k && b2 >= 0 && b2 < k)
                    acc += s[j + 1] * ws[j][c * k * k + a * k + b2];
            }
        }
        g_weq[c * 169 + t] = acc;
    }
}

__global__ void build_B_kernel()
{
    int c = blockIdx.x;
    for (int t = threadIdx.x; t < KTOT * 8; t += blockDim.x) {
        int k = t >> 3, n = t & 7;
        float v = 0.f;
        if (k < 260) {
            int ky  = k / 20;
            int c20 = k - ky * 20;
            int kx  = c20 - n;
            if (kx >= 0 && kx <= 12)
                v = g_weq[c * 169 + ky * 13 + kx];
        }
        g_B[c * (KTOT * 8) + t] = f2tf32(v);
    }
}

__global__ void __launch_bounds__(NTHR, 4) conv_tc(const float* __restrict__ x,
                                                   float* __restrict__ out)
{
    __shared__ uint32_t sA[2 * TILE];   // two padded 69x68 tiles, tf32 bits
    __shared__ uint32_t sB[KTOT * 8];   // 8448 B
    __shared__ float    sbias;

    int bid     = blockIdx.x;
    int c       = bid & (CC - 1);
    int pairIdx = bid >> 8;             // 0..15
    int ib0     = pairIdx * 2;
    int tid     = threadIdx.x;

    const float* xim0 = x + (size_t)(ib0 * CC + c) * (HW * HW);
    const float* xim1 = xim0 + (size_t)CC * (HW * HW);

    // Fill both padded tiles (zero halo; row 68 zero via iy>=56).
    for (int idx = tid; idx < 2 * TILE; idx += NTHR) {
        int e = idx, img = 0;
        if (e >= TILE) { img = 1; e -= TILE; }
        int r  = e / TCOLS;
        int cc2 = e - r * TCOLS;
        int iy = r - PAD, ix = cc2 - PAD;
        float v = 0.f;
        if ((unsigned)iy < (unsigned)HW && (unsigned)ix < (unsigned)HW)
            v = (img ? xim1 : xim0)[iy * HW + ix];
        sA[idx] = f2tf32(v);
    }
    for (int t = tid; t < KTOT * 8; t += NTHR)
        sB[t] = g_B[c * (KTOT * 8) + t];
    if (tid == 0) sbias = g_bias[c];
    __syncthreads();

    int warp = tid >> 5;                // xb = warp (0..6)
    int lane = tid & 31;
    int g    = lane >> 2;               // groupID 0..7
    int tig  = lane & 3;                // threadID-in-group
    int xb   = warp;

    float bb = sbias;

#pragma unroll 1
    for (int mt = 0; mt < 7; mt++) {
        int m    = mt * 16 + g;
        int img  = (m >= HW) ? 1 : 0;
        int y    = m - HW * img;
        int m2   = m + 8;
        int img2 = (m2 >= HW) ? 1 : 0;
        int y2   = m2 - HW * img2;

        int base0 = img * TILE + y * TCOLS + xb * 8;
        int d8    = (img2 * TILE + y2 * TCOLS) - (img * TILE + y * TCOLS);

        // Incremental (ky,c20) trackers; all lanes wrap in lockstep.
        int adr0 = base0 + tig;       int c0t = tig;       // a0/a1 (kk = k0+tig)
        int adr1 = base0 + tig + 4;   int c1t = tig + 4;   // a2/a3 (kk+4)
        int badr = tig * 8 + g;                            // B[k0+tig][g]

        float d0 = 0.f, d1 = 0.f, d2 = 0.f, d3 = 0.f;

#pragma unroll
        for (int ks = 0; ks < 33; ks++) {
            uint32_t a0 = sA[adr0],     a1 = sA[adr0 + d8];
            uint32_t a2 = sA[adr1],     a3 = sA[adr1 + d8];
            uint32_t b0 = sB[badr],     b1 = sB[badr + 32];

            asm volatile(
                "mma.sync.aligned.m16n8k8.row.col.f32.tf32.tf32.f32 "
                "{%0,%1,%2,%3}, {%4,%5,%6,%7}, {%8,%9}, {%0,%1,%2,%3};"
                : "+f"(d0), "+f"(d1), "+f"(d2), "+f"(d3)
                : "r"(a0), "r"(a1), "r"(a2), "r"(a3), "r"(b0), "r"(b1));

            adr0 += 8; c0t += 8; if (c0t >= 20) { c0t -= 20; adr0 += TCOLS - 20; }
            adr1 += 8; c1t += 8; if (c1t >= 20) { c1t -= 20; adr1 += TCOLS - 20; }
            badr += 64;
        }

        // D row m: (img,y); row m+8: (img2,y2). Cols 2*tig, 2*tig+1.
        float* o0 = out + (size_t)((ib0 + img)  * CC + c) * (HW * HW)
                        + y  * HW + xb * 8 + 2 * tig;
        float* o1 = out + (size_t)((ib0 + img2) * CC + c) * (HW * HW)
                        + y2 * HW + xb * 8 + 2 * tig;
        reinterpret_cast<float2*>(o0)[0] = make_float2(d0 + bb, d1 + bb);
        reinterpret_cast<float2*>(o1)[0] = make_float2(d2 + bb, d3 + bb);
    }
}

extern "C" void kernel_launch(void* const* d_in, const int* in_sizes, int n_in,
                              void* d_out, int out_size)
{
    const float* x    = (const float*)d_in[0];
    const float* lk_w = (const float*)d_in[1];
    const float* w0   = (const float*)d_in[2];
    const float* w1   = (const float*)d_in[3];
    const float* w2   = (const float*)d_in[4];
    const float* w3   = (const float*)d_in[5];
    const float* w4   = (const float*)d_in[6];
    const float* w5   = (const float*)d_in[7];
    const float* g    = (const float*)d_in[8];
    const float* b    = (const float*)d_in[9];
    const float* m    = (const float*)d_in[10];
    const float* v    = (const float*)d_in[11];
    float* out = (float*)d_out;

    prep_kernel<<<CC, 192>>>(lk_w, w0, w1, w2, w3, w4, w5, g, b, m, v);
    build_B_kernel<<<CC, 256>>>();

    int nimg = out_size / (HW * HW * CC);   // 32
    int grid = (nimg / 2) * CC;             // 4096 CTAs
    conv_tc<<<grid, NTHR>>>(x, out);
}